// round 2
// baseline (speedup 1.0000x reference)
#include <cuda_runtime.h>
#include <cstdint>

// Problem constants
#define BB   8
#define LL   512
#define DD   1024
#define SS   6144
#define MM   (BB * LL)     // 4096 GEMM rows
#define LP1  (LL + 1)      // 513 prefix rows

// Scratch (device globals: no allocation allowed)
__device__ float g_p[MM * DD];        // p = h @ W^T          (16 MB)
__device__ float g_g[BB * LP1 * DD];  // prefix sums of p     (16.8 MB)
__device__ int   g_is32;              // span_idx dtype flag

// ---------------------------------------------------------------------------
// helpers
// ---------------------------------------------------------------------------
__device__ __forceinline__ float tf32rna(float x) {
    uint32_t u;
    asm("cvt.rna.tf32.f32 %0, %1;" : "=r"(u) : "f"(x));
    return __uint_as_float(u);
}

__device__ __forceinline__ void mma_tf32(float c[4], const uint32_t a[4], const uint32_t b[2]) {
    asm volatile(
        "mma.sync.aligned.m16n8k8.row.col.f32.tf32.tf32.f32 "
        "{%0,%1,%2,%3}, {%4,%5,%6,%7}, {%8,%9}, {%0,%1,%2,%3};"
        : "+f"(c[0]), "+f"(c[1]), "+f"(c[2]), "+f"(c[3])
        : "r"(a[0]), "r"(a[1]), "r"(a[2]), "r"(a[3]),
          "r"(b[0]), "r"(b[1]));
}

// ---------------------------------------------------------------------------
// Kernel 1: p[m][n] = sum_d h[m][d] * W[n][d]   (tf32 tensor-core GEMM)
// M=4096, N=1024, K=1024. Block tile 128x128x32, 256 threads (8 warps, 4x2),
// warp tile 32x64. Register-staged double buffer, cvt.rna at STS time.
// KPAD=36 makes both fragment LDS and the STS.128 pattern bank-conflict-free.
// ---------------------------------------------------------------------------
#define BM 128
#define BN 128
#define BK 32
#define KPAD 36

__global__ void __launch_bounds__(256)
gemm_tf32_kernel(const float* __restrict__ A,   // h  [4096,1024]
                 const float* __restrict__ Wm,  // W  [1024,1024]
                 float* __restrict__ P)         // p  [4096,1024]
{
    __shared__ float As[BM * KPAD];
    __shared__ float Bs[BN * KPAD];

    const int tid  = threadIdx.x;
    const int warp = tid >> 5;
    const int lane = tid & 31;
    const int wm   = warp >> 1;   // 0..3
    const int wn   = warp & 1;    // 0..1
    const int m0   = blockIdx.x * BM;
    const int n0   = blockIdx.y * BN;

    // gmem->smem loading assignment: thread handles rows (tid>>3)+{0,32,64,96},
    // float4 column (tid&7)
    const int lr = tid >> 3;
    const int lc = (tid & 7) * 4;

    const float* Ag = A  + (size_t)(m0 + lr) * DD + lc;
    const float* Bg = Wm + (size_t)(n0 + lr) * DD + lc;

    float acc[2][8][4];
    #pragma unroll
    for (int mt = 0; mt < 2; mt++)
        #pragma unroll
        for (int nt = 0; nt < 8; nt++)
            #pragma unroll
            for (int r = 0; r < 4; r++) acc[mt][nt][r] = 0.0f;

    float4 ra[4], rb[4];
    #pragma unroll
    for (int j = 0; j < 4; j++) {
        ra[j] = *(const float4*)(Ag + (size_t)j * 32 * DD);
        rb[j] = *(const float4*)(Bg + (size_t)j * 32 * DD);
    }

    const int NKT = DD / BK;  // 32
    for (int kt = 0; kt < NKT; kt++) {
        // cvt + store staged tile to smem
        #pragma unroll
        for (int j = 0; j < 4; j++) {
            float4 a = ra[j], b = rb[j];
            a.x = tf32rna(a.x); a.y = tf32rna(a.y); a.z = tf32rna(a.z); a.w = tf32rna(a.w);
            b.x = tf32rna(b.x); b.y = tf32rna(b.y); b.z = tf32rna(b.z); b.w = tf32rna(b.w);
            *(float4*)(&As[(lr + j * 32) * KPAD + lc]) = a;
            *(float4*)(&Bs[(lr + j * 32) * KPAD + lc]) = b;
        }
        __syncthreads();

        // prefetch next K-tile while computing this one
        if (kt + 1 < NKT) {
            const int ko = (kt + 1) * BK;
            #pragma unroll
            for (int j = 0; j < 4; j++) {
                ra[j] = *(const float4*)(Ag + (size_t)j * 32 * DD + ko);
                rb[j] = *(const float4*)(Bg + (size_t)j * 32 * DD + ko);
            }
        }

        #pragma unroll
        for (int ks = 0; ks < 4; ks++) {
            const int k0 = ks * 8 + (lane & 3);
            const int rA = wm * 32 + (lane >> 2);

            uint32_t af[2][4];
            #pragma unroll
            for (int mt = 0; mt < 2; mt++) {
                const int r = rA + mt * 16;
                af[mt][0] = __float_as_uint(As[r       * KPAD + k0]);
                af[mt][1] = __float_as_uint(As[(r + 8) * KPAD + k0]);
                af[mt][2] = __float_as_uint(As[r       * KPAD + k0 + 4]);
                af[mt][3] = __float_as_uint(As[(r + 8) * KPAD + k0 + 4]);
            }
            uint32_t bf[8][2];
            #pragma unroll
            for (int nt = 0; nt < 8; nt++) {
                const int n = wn * 64 + nt * 8 + (lane >> 2);
                bf[nt][0] = __float_as_uint(Bs[n * KPAD + k0]);
                bf[nt][1] = __float_as_uint(Bs[n * KPAD + k0 + 4]);
            }
            #pragma unroll
            for (int mt = 0; mt < 2; mt++)
                #pragma unroll
                for (int nt = 0; nt < 8; nt++)
                    mma_tf32(acc[mt][nt], af[mt], bf[nt]);
        }
        __syncthreads();
    }

    // epilogue: write p
    const int mrow = m0 + wm * 32 + (lane >> 2);
    const int ncol = n0 + wn * 64 + (lane & 3) * 2;
    #pragma unroll
    for (int mt = 0; mt < 2; mt++) {
        #pragma unroll
        for (int nt = 0; nt < 8; nt++) {
            const int r = mrow + mt * 16;
            const int c = ncol + nt * 8;
            float2 v0 = make_float2(acc[mt][nt][0], acc[mt][nt][1]);
            float2 v1 = make_float2(acc[mt][nt][2], acc[mt][nt][3]);
            *(float2*)(&P[(size_t)r       * DD + c]) = v0;
            *(float2*)(&P[(size_t)(r + 8) * DD + c]) = v1;
        }
    }
}

// ---------------------------------------------------------------------------
// Kernel 2: exclusive prefix sum over t of p, per (batch, feature).
// g[b][0][e] = 0; g[b][t+1][e] = g[b][t][e] + p[b][t][e].
// One thread per (b, e): 8192 threads. Unroll-32 prefetch for MLP.
// Also: block 0 / thread 0 detects span_idx dtype (int64 vs int32).
// ---------------------------------------------------------------------------
__global__ void prefix_kernel(const float* __restrict__ P,
                              float* __restrict__ G,
                              const int* __restrict__ idx_words)
{
    if (blockIdx.x == 0 && threadIdx.x == 0) {
        // If int64: odd 32-bit words are the zero high halves of values < 512.
        // If int32: odd words are 'end' values -- all-zero is impossible.
        int any = 0;
        #pragma unroll
        for (int j = 0; j < 64; j++) any |= idx_words[2 * j + 1];
        g_is32 = (any != 0) ? 1 : 0;
    }

    const int gidx = blockIdx.x * blockDim.x + threadIdx.x;  // 0..8191
    const int b = gidx >> 10;
    const int e = gidx & (DD - 1);

    const float* p = P + (size_t)b * LL * DD + e;
    float*       g = G + (size_t)b * LP1 * DD + e;

    float c = 0.0f;
    g[0] = 0.0f;
    for (int t = 0; t < LL; t += 32) {
        float v[32];
        #pragma unroll
        for (int j = 0; j < 32; j++) v[j] = p[(size_t)(t + j) * DD];
        #pragma unroll
        for (int j = 0; j < 32; j++) {
            c += v[j];
            g[(size_t)(t + j + 1) * DD] = c;
        }
    }
}

// ---------------------------------------------------------------------------
// Kernel 3: epilogue. One block (256 thr) per span; each thread one float4.
// out[span][d] = relu((g[b][e+1][d] - g[b][s][d]) * inv_cnt + bias[d])
// Invalid spans (s > e): inv_cnt = 0 -> relu(bias).
// ---------------------------------------------------------------------------
__global__ void __launch_bounds__(256)
epilogue_kernel(const int* __restrict__ idx_words,
                const float* __restrict__ G,
                const float* __restrict__ bias,
                float* __restrict__ out)
{
    const int span = blockIdx.x;          // 0 .. B*S-1
    const int b    = span / SS;

    int w0, w1;
    if (g_is32) {
        w0 = idx_words[2 * span];
        w1 = idx_words[2 * span + 1];
    } else {
        w0 = idx_words[4 * span];
        w1 = idx_words[4 * span + 2];
    }
    int s0 = min(max(w0, 0), LL - 1);
    int e0 = min(max(w1, 0), LL - 1);
    const bool  valid = (s0 <= e0);
    const float inv   = valid ? (1.0f / (float)(e0 - s0 + 1)) : 0.0f;

    const float* gs = G + ((size_t)b * LP1 + s0)     * DD;
    const float* ge = G + ((size_t)b * LP1 + e0 + 1) * DD;

    const int d = threadIdx.x * 4;
    float4 a  = *(const float4*)(ge + d);
    float4 c  = *(const float4*)(gs + d);
    float4 bb = *(const float4*)(bias + d);

    float4 o;
    o.x = fmaxf(fmaf(a.x - c.x, inv, bb.x), 0.0f);
    o.y = fmaxf(fmaf(a.y - c.y, inv, bb.y), 0.0f);
    o.z = fmaxf(fmaf(a.z - c.z, inv, bb.z), 0.0f);
    o.w = fmaxf(fmaf(a.w - c.w, inv, bb.w), 0.0f);

    *(float4*)(out + (size_t)span * DD + d) = o;
}

// ---------------------------------------------------------------------------
// launch
// ---------------------------------------------------------------------------
extern "C" void kernel_launch(void* const* d_in, const int* in_sizes, int n_in,
                              void* d_out, int out_size)
{
    // Match inputs by element count (robust to metadata ordering):
    //   h: 4,194,304   span_idx: 98,304   W: 1,048,576   b: 1,024
    const float* h   = nullptr;
    const void*  idx = nullptr;
    const float* W   = nullptr;
    const float* bia = nullptr;
    for (int i = 0; i < n_in; i++) {
        switch (in_sizes[i]) {
            case BB * LL * DD:   h   = (const float*)d_in[i]; break;
            case BB * SS * 2:    idx = d_in[i];               break;
            case DD * DD:        W   = (const float*)d_in[i]; break;
            case DD:             bia = (const float*)d_in[i]; break;
            default: break;
        }
    }

    float* p_scratch;  cudaGetSymbolAddress((void**)&p_scratch, g_p);
    float* g_scratch;  cudaGetSymbolAddress((void**)&g_scratch, g_g);

    dim3 gemm_grid(MM / BM, DD / BN);  // 32 x 8
    gemm_tf32_kernel<<<gemm_grid, 256>>>(h, W, p_scratch);

    prefix_kernel<<<(BB * DD) / 64, 64>>>(p_scratch, g_scratch, (const int*)idx);

    epilogue_kernel<<<BB * SS, 256>>>((const int*)idx, g_scratch, bia, (float*)d_out);
}